// round 10
// baseline (speedup 1.0000x reference)
#include <cuda_runtime.h>
#include <cuda_bf16.h>
#include <cstdint>
#include <cstddef>

typedef __nv_bfloat16 bf16;

// Problem constants
#define Bq   2
#define Nt   8192
#define Dd   1024
#define Hh   16
#define DH   64
#define Mrows (Bq * Nt)
#define NSPLIT 16

// ---------------- scratch ---------------------------------------------------
__device__ float g_qk[(size_t)Mrows * Dd];
__device__ bf16  g_xh[(size_t)Mrows * Dd];
__device__ bf16  g_xl[(size_t)Mrows * Dd];
__device__ bf16  g_wth[(size_t)Dd * Dd];
__device__ bf16  g_wtl[(size_t)Dd * Dd];
__device__ bf16  g_wvh[(size_t)Dd * Dd];
__device__ bf16  g_wvl[(size_t)Dd * Dd];
__device__ bf16  g_mth[(size_t)Bq * Dd * Dd];
__device__ bf16  g_mtl[(size_t)Bq * Dd * Dd];
__device__ float g_ntf[(size_t)Bq * Dd * Dd];
__device__ bf16  g_nth[(size_t)Bq * Dd * Dd];
__device__ bf16  g_ntl[(size_t)Bq * Dd * Dd];
__device__ float g_gpart[(size_t)Bq * Hh * NSPLIT * DH * DH];
__device__ float g_attn [(size_t)Bq * Hh * DH * DH];

// ---------------- PTX helpers -------------------------------------------------
__device__ __forceinline__ uint32_t smem_u32(const void* p) {
    uint32_t a;
    asm("{ .reg .u64 t; cvta.to.shared.u64 t, %1; cvt.u32.u64 %0, t; }"
        : "=r"(a) : "l"(p));
    return a;
}

#define LDM4(r, addr)                                                          \
    asm volatile("ldmatrix.sync.aligned.m8n8.x4.shared.b16 {%0,%1,%2,%3}, [%4];" \
        : "=r"((r)[0]), "=r"((r)[1]), "=r"((r)[2]), "=r"((r)[3]) : "r"(addr))

__device__ __forceinline__ void mma16(float* c, const uint32_t* a, const uint32_t* b) {
    asm volatile(
        "mma.sync.aligned.m16n8k16.row.col.f32.bf16.bf16.f32 "
        "{%0,%1,%2,%3}, {%4,%5,%6,%7}, {%8,%9}, {%0,%1,%2,%3};"
        : "+f"(c[0]), "+f"(c[1]), "+f"(c[2]), "+f"(c[3])
        : "r"(a[0]), "r"(a[1]), "r"(a[2]), "r"(a[3]), "r"(b[0]), "r"(b[1]));
}

#define CPA(dst, src) \
    asm volatile("cp.async.cg.shared.global [%0], [%1], 16;" :: "r"(dst), "l"(src) : "memory")
#define CPC() asm volatile("cp.async.commit_group;" ::: "memory")
#define CPW(n) asm volatile("cp.async.wait_group %0;" :: "n"(n) : "memory")

#define REDADD(ptr, v) \
    asm volatile("red.global.add.f32 [%0], %1;" :: "l"(ptr), "f"(v) : "memory")

__device__ __forceinline__ uint32_t swz(uint32_t row, uint32_t c) {
    return row * 64u + (((c ^ ((row >> 1) & 3u)) & 3u) << 4);
}

// ---------------- bf16 split GEMM, 128x128 tile, 256 threads, 2 CTAs/SM --------
// C[m,n] = sum_k A[m,k]*BT[n,k]; planes row-major k-contiguous (ld=1024).
// BK=32, 3 stages, 8 warps (2m x 4n), warp tile 64x32.
#define BK 32
#define PLANE_B 8192                  // 128 rows * 64 B
#define STAGE_B (4 * PLANE_B)         // 32768
#define NSTAGE  3
#define SMB     (NSTAGE * STAGE_B)    // 98304
#define OFF_AL  PLANE_B
#define OFF_BH  (2 * PLANE_B)
#define OFF_BL  (3 * PLANE_B)

template <int ATOMIC>
__global__ __launch_bounds__(256, 2)
void mma_gemm(const bf16* __restrict__ gAh, const bf16* __restrict__ gAl, size_t aZ,
              const bf16* __restrict__ gBh, const bf16* __restrict__ gBl, size_t bZ,
              float* Cf0, float* Cf1,
              int nxt, int ksteps)
{
    extern __shared__ __align__(16) char smc[];
    const int z = blockIdx.z;
    const int ks0 = (blockIdx.x / nxt) * ksteps;
    const int bn  = (blockIdx.x % nxt) * 128;
    const bf16* Ah = gAh + (size_t)z * aZ;
    const bf16* Al = gAl + (size_t)z * aZ;
    const bf16* Bh = gBh + (size_t)z * bZ;
    const bf16* Bl = gBl + (size_t)z * bZ;
    float* Cf = z ? Cf1 : Cf0;

    const int bm = blockIdx.y * 128;
    const int tid = threadIdx.x;
    const int wid = tid >> 5;
    const int lid = tid & 31;
    const int g = lid >> 2;
    const int t = lid & 3;
    const int wm = (wid >> 2) * 64;     // 2 m-groups
    const int wn = (wid & 3) * 32;      // 4 n-groups

    const uint32_t sbase = smem_u32(smc);

    // cp.async geometry: thread -> rows r, r+64 of each 128-row plane
    const uint32_t rA = (uint32_t)tid >> 2;      // 0..63
    const uint32_t cC = (uint32_t)tid & 3;
    const uint32_t rA1 = rA + 64;
    const uint32_t sw0 = swz(rA, cC);
    const uint32_t sw1 = swz(rA1, cC);
    const bf16* gah0 = Ah + (size_t)(bm + rA) * 1024 + cC * 8;
    const bf16* gah1 = Ah + (size_t)(bm + rA1) * 1024 + cC * 8;
    const bf16* gal0 = Al + (size_t)(bm + rA) * 1024 + cC * 8;
    const bf16* gal1 = Al + (size_t)(bm + rA1) * 1024 + cC * 8;
    const bf16* gbh0 = Bh + (size_t)(bn + rA) * 1024 + cC * 8;
    const bf16* gbh1 = Bh + (size_t)(bn + rA1) * 1024 + cC * 8;
    const bf16* gbl0 = Bl + (size_t)(bn + rA) * 1024 + cC * 8;
    const bf16* gbl1 = Bl + (size_t)(bn + rA1) * 1024 + cC * 8;

    auto issue = [&](int k0, int st) {
        uint32_t sb2 = sbase + (uint32_t)st * STAGE_B;
        CPA(sb2 + sw0,          gah0 + k0);
        CPA(sb2 + sw1,          gah1 + k0);
        CPA(sb2 + OFF_AL + sw0, gal0 + k0);
        CPA(sb2 + OFF_AL + sw1, gal1 + k0);
        CPA(sb2 + OFF_BH + sw0, gbh0 + k0);
        CPA(sb2 + OFF_BH + sw1, gbh1 + k0);
        CPA(sb2 + OFF_BL + sw0, gbl0 + k0);
        CPA(sb2 + OFF_BL + sw1, gbl1 + k0);
    };

    float acc[4][4][4];
    #pragma unroll
    for (int i = 0; i < 4; i++)
        #pragma unroll
        for (int j = 0; j < 4; j++)
            #pragma unroll
            for (int e = 0; e < 4; e++) acc[i][j][e] = 0.0f;

    uint32_t arow[4], brow[2];
    #pragma unroll
    for (int i = 0; i < 4; i++) arow[i] = (uint32_t)(wm + i * 16 + (lid & 15));
    #pragma unroll
    for (int jp = 0; jp < 2; jp++)
        brow[jp] = (uint32_t)(wn + jp * 16 + (lid & 7) + ((lid >> 4) << 3));
    const uint32_t aco = (uint32_t)(lid >> 4);
    const uint32_t bco = (uint32_t)((lid >> 3) & 1);

    auto compute = [&](int buf) {
        const uint32_t bb = sbase + (uint32_t)buf * STAGE_B;
        #pragma unroll
        for (int ks2 = 0; ks2 < 2; ks2++) {
            uint32_t ah[4][4], al[4][4], bh[4][2], bl[4][2];
            #pragma unroll
            for (int i = 0; i < 4; i++) {
                uint32_t off = swz(arow[i], ks2 * 2 + aco);
                LDM4(ah[i], bb + off);
                LDM4(al[i], bb + OFF_AL + off);
            }
            #pragma unroll
            for (int jp = 0; jp < 2; jp++) {
                uint32_t off = swz(brow[jp], ks2 * 2 + bco);
                uint32_t r[4];
                LDM4(r, bb + OFF_BH + off);
                bh[2 * jp][0] = r[0]; bh[2 * jp][1] = r[1];
                bh[2 * jp + 1][0] = r[2]; bh[2 * jp + 1][1] = r[3];
                LDM4(r, bb + OFF_BL + off);
                bl[2 * jp][0] = r[0]; bl[2 * jp][1] = r[1];
                bl[2 * jp + 1][0] = r[2]; bl[2 * jp + 1][1] = r[3];
            }
            #pragma unroll
            for (int i = 0; i < 4; i++)
                #pragma unroll
                for (int j = 0; j < 4; j++) mma16(acc[i][j], ah[i], bl[j]);
            #pragma unroll
            for (int i = 0; i < 4; i++)
                #pragma unroll
                for (int j = 0; j < 4; j++) mma16(acc[i][j], al[i], bh[j]);
            #pragma unroll
            for (int i = 0; i < 4; i++)
                #pragma unroll
                for (int j = 0; j < 4; j++) mma16(acc[i][j], ah[i], bh[j]);
        }
    };

    const int NS = ksteps;

    issue(ks0 * BK, 0); CPC();
    issue((ks0 + 1) * BK, 1); CPC();

    #pragma unroll 1
    for (int s = 0; s < NS; s++) {
        if (s < NS - 1) { CPW(1); } else { CPW(0); }
        __syncthreads();
        compute(s % 3);
        if (s + 2 < NS) { issue((ks0 + s + 2) * BK, (s + 2) % 3); CPC(); }
    }

    // epilogue
    if (ATOMIC) {
        #pragma unroll
        for (int i = 0; i < 4; i++) {
            int row = bm + wm + i * 16 + g;
            #pragma unroll
            for (int j = 0; j < 4; j++) {
                int col = bn + wn + j * 8 + 2 * t;
                float* p0 = Cf + (size_t)row * 1024 + col;
                float* p1 = Cf + (size_t)(row + 8) * 1024 + col;
                REDADD(p0,     acc[i][j][0]);
                REDADD(p0 + 1, acc[i][j][1]);
                REDADD(p1,     acc[i][j][2]);
                REDADD(p1 + 1, acc[i][j][3]);
            }
        }
    } else {
        #pragma unroll
        for (int i = 0; i < 4; i++) {
            int row = bm + wm + i * 16 + g;
            #pragma unroll
            for (int j = 0; j < 4; j++) {
                int col = bn + wn + j * 8 + 2 * t;
                *(float2*)(Cf + (size_t)row * 1024 + col) =
                    make_float2(acc[i][j][0], acc[i][j][1]);
                *(float2*)(Cf + (size_t)(row + 8) * 1024 + col) =
                    make_float2(acc[i][j][2], acc[i][j][3]);
            }
        }
    }
}

// ---------------- split fp32 -> bf16 hi/lo planes ------------------------------
__global__ __launch_bounds__(256)
void split_f32(const float* __restrict__ src, bf16* __restrict__ h, bf16* __restrict__ l)
{
    size_t i = ((size_t)blockIdx.x * 256 + threadIdx.x) * 4;
    float4 v = *(const float4*)(src + i);
    bf16 h0 = __float2bfloat16_rn(v.x), h1 = __float2bfloat16_rn(v.y);
    bf16 h2 = __float2bfloat16_rn(v.z), h3 = __float2bfloat16_rn(v.w);
    bf16 l0 = __float2bfloat16_rn(v.x - __bfloat162float(h0));
    bf16 l1 = __float2bfloat16_rn(v.y - __bfloat162float(h1));
    bf16 l2 = __float2bfloat16_rn(v.z - __bfloat162float(h2));
    bf16 l3 = __float2bfloat16_rn(v.w - __bfloat162float(h3));
    __nv_bfloat162 a, b;
    a.x = h0; a.y = h1; b.x = h2; b.y = h3;
    *(__nv_bfloat162*)(h + i) = a; *(__nv_bfloat162*)(h + i + 2) = b;
    a.x = l0; a.y = l1; b.x = l2; b.y = l3;
    *(__nv_bfloat162*)(l + i) = a; *(__nv_bfloat162*)(l + i + 2) = b;
}

// ---------------- Wqk transpose + split ----------------------------------------
__global__ __launch_bounds__(256)
void transpose_w(const float* __restrict__ W, bf16* __restrict__ WTh, bf16* __restrict__ WTl)
{
    __shared__ float tbuf[32][33];
    int bx = blockIdx.x * 32, by = blockIdx.y * 32;
    int tx = threadIdx.x & 31, ty = threadIdx.x >> 5;
    #pragma unroll
    for (int i = 0; i < 4; i++) {
        int r = ty + i * 8;
        tbuf[r][tx] = W[(size_t)(by + r) * Dd + bx + tx];
    }
    __syncthreads();
    #pragma unroll
    for (int i = 0; i < 4; i++) {
        int r = ty + i * 8;
        float v = tbuf[tx][r];
        bf16 h = __float2bfloat16_rn(v);
        bf16 l = __float2bfloat16_rn(v - __bfloat162float(h));
        size_t o = (size_t)(bx + r) * Dd + by + tx;
        WTh[o] = h; WTl[o] = l;
    }
}

// ---------------- Gram partials (fp32, float4 LDS) ------------------------------
__global__ __launch_bounds__(256)
void gram_partial(const float* __restrict__ QK, float* __restrict__ Gpart)
{
    const int bh = blockIdx.x;
    const int sp = blockIdx.y;
    const int b = bh >> 4;
    const int h = bh & 15;
    const float* A = QK + (size_t)b * Nt * Dd + h * DH;

    __shared__ float As[32][64];
    const int tid = threadIdx.x;
    const int tx = tid & 15, ty = tid >> 4;

    float acc[4][4];
    #pragma unroll
    for (int i = 0; i < 4; i++)
        #pragma unroll
        for (int j = 0; j < 4; j++) acc[i][j] = 0.0f;

    const int n0base = sp * (Nt / NSPLIT);
    for (int n0 = n0base; n0 < n0base + Nt / NSPLIT; n0 += 32) {
        #pragma unroll
        for (int i = 0; i < 2; i++) {
            int idx = tid + i * 256;
            int r = idx >> 4;
            int c4 = (idx & 15) * 4;
            *(float4*)&As[r][c4] = *(const float4*)(A + (size_t)(n0 + r) * Dd + c4);
        }
        __syncthreads();
        #pragma unroll
        for (int kk = 0; kk < 32; kk++) {
            float4 rc = *(float4*)&As[kk][ty * 4];
            float4 rd = *(float4*)&As[kk][tx * 4];
            float rcv[4] = {rc.x, rc.y, rc.z, rc.w};
            float rdv[4] = {rd.x, rd.y, rd.z, rd.w};
            #pragma unroll
            for (int i = 0; i < 4; i++)
                #pragma unroll
                for (int j = 0; j < 4; j++)
                    acc[i][j] += rcv[i] * rdv[j];
        }
        __syncthreads();
    }

    float* gp = Gpart + ((size_t)bh * NSPLIT + sp) * (DH * DH);
    #pragma unroll
    for (int i = 0; i < 4; i++)
        #pragma unroll
        for (int j = 0; j < 4; j++)
            gp[(ty * 4 + i) * DH + tx * 4 + j] = acc[i][j];
}

// ---------------- reduce + softmax ----------------------------------------------
__global__ __launch_bounds__(256)
void softmax_kernel(const float* __restrict__ Gpart,
                    const float* __restrict__ tau,
                    float* __restrict__ attn)
{
    const int bh = blockIdx.x;
    const int h = bh & 15;
    __shared__ float G[DH * DH];
    const int tid = threadIdx.x;

    const float* base = Gpart + (size_t)bh * NSPLIT * (DH * DH);
    for (int e = tid; e < DH * DH; e += 256) {
        float s = 0.0f;
        #pragma unroll
        for (int p = 0; p < NSPLIT; p++) s += base[(size_t)p * (DH * DH) + e];
        G[e] = s;
    }
    __syncthreads();

    if (tid < DH) {
        const int c = tid;
        const float tauh = tau[h];
        const float scale = 0.011048543456039806f;
        const float qc = G[c * DH + c];
        float l[DH];
        float mx = -1e30f;
        #pragma unroll 8
        for (int d = 0; d < DH; d++) {
            float v = (2.0f * G[c * DH + d] - qc - G[d * DH + d]) * scale * tauh;
            l[d] = v;
            mx = fmaxf(mx, v);
        }
        float sum = 0.0f;
        #pragma unroll 8
        for (int d = 0; d < DH; d++) { float e = __expf(l[d] - mx); l[d] = e; sum += e; }
        const float inv = 1.0f / sum;
        float* ap = attn + (size_t)bh * (DH * DH) + c * DH;
        #pragma unroll 8
        for (int d = 0; d < DH; d++) ap[d] = l[d] * inv;
    }
}

// ---------------- fold attn into W_out, emit split M^T ---------------------------
__global__ __launch_bounds__(256)
void build_mT(const float* __restrict__ attn,
              const float* __restrict__ Wout,
              bf16* __restrict__ MTh, bf16* __restrict__ MTl)
{
    const int bh = blockIdx.y;
    const int b = bh >> 4, h = bh & 15;
    const int j0 = blockIdx.x * 128;

    __shared__ float Asm[DH * DH];
    __shared__ float Ws[DH][128];

    const int tid = threadIdx.x;
    const float* ap = attn + (size_t)bh * (DH * DH);
    for (int e = tid; e < DH * DH; e += 256) Asm[e] = ap[e];

    #pragma unroll
    for (int i = 0; i < 8; i++) {
        int idx = tid + i * 256;
        int r = idx >> 5;
        int c4 = (idx & 31) * 4;
        *(float4*)&Ws[r][c4] =
            *(const float4*)(Wout + (size_t)(h * DH + r) * Dd + j0 + c4);
    }
    __syncthreads();

    const int tx = tid & 15, ty = tid >> 4;
    float acc[8][4];
    #pragma unroll
    for (int i = 0; i < 8; i++)
        #pragma unroll
        for (int j = 0; j < 4; j++) acc[i][j] = 0.0f;

    for (int c = 0; c < DH; c++) {
        float4 av = *(float4*)&Asm[c * DH + tx * 4];
        #pragma unroll
        for (int i = 0; i < 8; i++) {
            float w = Ws[c][ty * 8 + i];
            acc[i][0] += w * av.x;
            acc[i][1] += w * av.y;
            acc[i][2] += w * av.z;
            acc[i][3] += w * av.w;
        }
    }

    bf16* Mh = MTh + (size_t)b * Dd * Dd;
    bf16* Ml = MTl + (size_t)b * Dd * Dd;
    #pragma unroll
    for (int i = 0; i < 8; i++) {
        int j = j0 + ty * 8 + i;
        size_t o = (size_t)j * Dd + h * DH + tx * 4;
        #pragma unroll
        for (int e = 0; e < 4; e++) {
            float v = acc[i][e];
            bf16 hh = __float2bfloat16_rn(v);
            bf16 ll = __float2bfloat16_rn(v - __bfloat162float(hh));
            Mh[o + e] = hh; Ml[o + e] = ll;
        }
    }
}

// ----------------------------------------------------------------------------------
extern "C" void kernel_launch(void* const* d_in, const int* in_sizes, int n_in,
                              void* d_out, int out_size)
{
    const float* x    = (const float*)d_in[0];
    const float* Wqk  = (const float*)d_in[1];
    const float* Wv   = (const float*)d_in[2];
    const float* Wout = (const float*)d_in[3];
    const float* tau  = (const float*)d_in[4];
    float* out = (float*)d_out;

    void *pqk, *pxh, *pxl, *pwth, *pwtl, *pwvh, *pwvl, *pmth, *pmtl,
         *pntf, *pnth, *pntl, *pg, *pa;
    cudaGetSymbolAddress(&pqk, g_qk);
    cudaGetSymbolAddress(&pxh, g_xh);
    cudaGetSymbolAddress(&pxl, g_xl);
    cudaGetSymbolAddress(&pwth, g_wth);
    cudaGetSymbolAddress(&pwtl, g_wtl);
    cudaGetSymbolAddress(&pwvh, g_wvh);
    cudaGetSymbolAddress(&pwvl, g_wvl);
    cudaGetSymbolAddress(&pmth, g_mth);
    cudaGetSymbolAddress(&pmtl, g_mtl);
    cudaGetSymbolAddress(&pntf, g_ntf);
    cudaGetSymbolAddress(&pnth, g_nth);
    cudaGetSymbolAddress(&pntl, g_ntl);
    cudaGetSymbolAddress(&pg, g_gpart);
    cudaGetSymbolAddress(&pa, g_attn);

    float* QK = (float*)pqk;
    bf16 *Xh = (bf16*)pxh, *Xl = (bf16*)pxl;
    bf16 *WTh = (bf16*)pwth, *WTl = (bf16*)pwtl;
    bf16 *WVh = (bf16*)pwvh, *WVl = (bf16*)pwvl;
    bf16 *MTh = (bf16*)pmth, *MTl = (bf16*)pmtl;
    float* NTf = (float*)pntf;
    bf16 *NTh = (bf16*)pnth, *NTl = (bf16*)pntl;
    float* Gp = (float*)pg;
    float* At = (float*)pa;

    cudaFuncSetAttribute(mma_gemm<0>, cudaFuncAttributeMaxDynamicSharedMemorySize, SMB);
    cudaFuncSetAttribute(mma_gemm<1>, cudaFuncAttributeMaxDynamicSharedMemorySize, SMB);

    // 0a: split X
    split_f32<<<(size_t)Mrows * Dd / 1024, 256>>>(x, Xh, Xl);
    // 0b: split Wv (row-major == n-major B for NT GEMM)
    split_f32<<<(size_t)Dd * Dd / 1024, 256>>>(Wv, WVh, WVl);
    // 0c: transpose + split Wqk
    transpose_w<<<dim3(32, 32), 256>>>(Wqk, WTh, WTl);
    // 1: QK = X @ Wqk  (no split-K, 2 CTAs/SM)
    mma_gemm<0><<<dim3(8, 128, 1), 256, SMB>>>(Xh, Xl, 0, WTh, WTl, 0,
                                               QK, QK, 8, 32);
    // 2: Gram partials
    gram_partial<<<dim3(32, NSPLIT), 256>>>(QK, Gp);
    // 3: reduce + softmax
    softmax_kernel<<<32, 256>>>(Gp, tau, At);
    // 4: fold attn into W_out (transposed, split)
    build_mT<<<dim3(8, 32), 256>>>(At, Wout, MTh, MTl);
    // 5: NT_b = MT_b @ Wv^T   (split-K=4, atomic fp32)
    cudaMemsetAsync(NTf, 0, (size_t)Bq * Dd * Dd * sizeof(float));
    mma_gemm<1><<<dim3(32, 8, 2), 256, SMB>>>(MTh, MTl, (size_t)Dd * Dd,
                                              WVh, WVl, 0,
                                              NTf, NTf + (size_t)Dd * Dd,
                                              8, 8);
    // 5b: split NT to bf16 planes
    split_f32<<<(size_t)Bq * Dd * Dd / 1024, 256>>>(NTf, NTh, NTl);
    // 6: out_b = X_b @ N_b
    mma_gemm<0><<<dim3(8, 64, 2), 256, SMB>>>(Xh, Xl, (size_t)Nt * Dd,
                                              NTh, NTl, (size_t)Dd * Dd,
                                              out, out + (size_t)Nt * Dd, 8, 32);
}

// round 11
// speedup vs baseline: 1.0644x; 1.0644x over previous
#include <cuda_runtime.h>
#include <cuda_bf16.h>
#include <cstdint>
#include <cstddef>

typedef __nv_bfloat16 bf16;

// Problem constants
#define Bq   2
#define Nt   8192
#define Dd   1024
#define Hh   16
#define DH   64
#define Mrows (Bq * Nt)
#define NSPLIT 16

// ---------------- scratch ---------------------------------------------------
__device__ bf16  g_xh[(size_t)Mrows * Dd];
__device__ bf16  g_xl[(size_t)Mrows * Dd];
__device__ bf16  g_qkth[(size_t)Bq * Dd * Nt];   // QK^T split planes [b][c][tok]
__device__ bf16  g_qktl[(size_t)Bq * Dd * Nt];
__device__ bf16  g_wth[(size_t)Dd * Dd];
__device__ bf16  g_wtl[(size_t)Dd * Dd];
__device__ bf16  g_wvh[(size_t)Dd * Dd];
__device__ bf16  g_wvl[(size_t)Dd * Dd];
__device__ bf16  g_mth[(size_t)Bq * Dd * Dd];
__device__ bf16  g_mtl[(size_t)Bq * Dd * Dd];
__device__ float g_ntf[(size_t)Bq * Dd * Dd];
__device__ bf16  g_nth[(size_t)Bq * Dd * Dd];
__device__ bf16  g_ntl[(size_t)Bq * Dd * Dd];
__device__ float g_gpart[(size_t)Bq * Hh * NSPLIT * DH * DH];
__device__ float g_attn [(size_t)Bq * Hh * DH * DH];

// ---------------- PTX helpers -------------------------------------------------
__device__ __forceinline__ uint32_t smem_u32(const void* p) {
    uint32_t a;
    asm("{ .reg .u64 t; cvta.to.shared.u64 t, %1; cvt.u32.u64 %0, t; }"
        : "=r"(a) : "l"(p));
    return a;
}

#define LDM4(r, addr)                                                          \
    asm volatile("ldmatrix.sync.aligned.m8n8.x4.shared.b16 {%0,%1,%2,%3}, [%4];" \
        : "=r"((r)[0]), "=r"((r)[1]), "=r"((r)[2]), "=r"((r)[3]) : "r"(addr))

__device__ __forceinline__ void mma16(float* c, const uint32_t* a, const uint32_t* b) {
    asm volatile(
        "mma.sync.aligned.m16n8k16.row.col.f32.bf16.bf16.f32 "
        "{%0,%1,%2,%3}, {%4,%5,%6,%7}, {%8,%9}, {%0,%1,%2,%3};"
        : "+f"(c[0]), "+f"(c[1]), "+f"(c[2]), "+f"(c[3])
        : "r"(a[0]), "r"(a[1]), "r"(a[2]), "r"(a[3]), "r"(b[0]), "r"(b[1]));
}

#define CPA(dst, src) \
    asm volatile("cp.async.cg.shared.global [%0], [%1], 16;" :: "r"(dst), "l"(src) : "memory")
#define CPC() asm volatile("cp.async.commit_group;" ::: "memory")
#define CPW(n) asm volatile("cp.async.wait_group %0;" :: "n"(n) : "memory")

#define REDADD(ptr, v) \
    asm volatile("red.global.add.f32 [%0], %1;" :: "l"(ptr), "f"(v) : "memory")

__device__ __forceinline__ uint32_t swz(uint32_t row, uint32_t c) {
    return row * 64u + (((c ^ ((row >> 1) & 3u)) & 3u) << 4);
}
// 128-byte-pitch swizzle (8 chunks of 16B per row)
__device__ __forceinline__ uint32_t swz128(uint32_t row, uint32_t c) {
    return row * 128u + (((c ^ (row & 7u)) & 7u) << 4);
}

// ---------------- bf16 split GEMM, 128x128 tile, 256 threads, 2 CTAs/SM --------
// C[m,n] = sum_k A[m,k]*BT[n,k]; planes row-major k-contiguous (ld=1024).
// MODE 0: fp32 store; MODE 1: fp32 red.add; MODE 2: split-bf16 QKT store
//          (row=channel, col=global token; batch folded from col).
#define BK 32
#define PLANE_B 8192
#define STAGE_B (4 * PLANE_B)
#define NSTAGE  3
#define SMB     (NSTAGE * STAGE_B)    // 98304
#define OFF_AL  PLANE_B
#define OFF_BH  (2 * PLANE_B)
#define OFF_BL  (3 * PLANE_B)

template <int MODE>
__global__ __launch_bounds__(256, 2)
void mma_gemm(const bf16* __restrict__ gAh, const bf16* __restrict__ gAl, size_t aZ,
              const bf16* __restrict__ gBh, const bf16* __restrict__ gBl, size_t bZ,
              float* Cf0, float* Cf1, bf16* Ch, bf16* Cl,
              int nxt, int ksteps)
{
    extern __shared__ __align__(16) char smc[];
    const int z = blockIdx.z;
    const int ks0 = (blockIdx.x / nxt) * ksteps;
    const int bn  = (blockIdx.x % nxt) * 128;
    const bf16* Ah = gAh + (size_t)z * aZ;
    const bf16* Al = gAl + (size_t)z * aZ;
    const bf16* Bh = gBh + (size_t)z * bZ;
    const bf16* Bl = gBl + (size_t)z * bZ;
    float* Cf = z ? Cf1 : Cf0;

    const int bm = blockIdx.y * 128;
    const int tid = threadIdx.x;
    const int wid = tid >> 5;
    const int lid = tid & 31;
    const int g = lid >> 2;
    const int t = lid & 3;
    const int wm = (wid >> 2) * 64;
    const int wn = (wid & 3) * 32;

    const uint32_t sbase = smem_u32(smc);

    const uint32_t rA = (uint32_t)tid >> 2;
    const uint32_t cC = (uint32_t)tid & 3;
    const uint32_t rA1 = rA + 64;
    const uint32_t sw0 = swz(rA, cC);
    const uint32_t sw1 = swz(rA1, cC);
    const bf16* gah0 = Ah + (size_t)(bm + rA) * 1024 + cC * 8;
    const bf16* gah1 = Ah + (size_t)(bm + rA1) * 1024 + cC * 8;
    const bf16* gal0 = Al + (size_t)(bm + rA) * 1024 + cC * 8;
    const bf16* gal1 = Al + (size_t)(bm + rA1) * 1024 + cC * 8;
    const bf16* gbh0 = Bh + (size_t)(bn + rA) * 1024 + cC * 8;
    const bf16* gbh1 = Bh + (size_t)(bn + rA1) * 1024 + cC * 8;
    const bf16* gbl0 = Bl + (size_t)(bn + rA) * 1024 + cC * 8;
    const bf16* gbl1 = Bl + (size_t)(bn + rA1) * 1024 + cC * 8;

    auto issue = [&](int k0, int st) {
        uint32_t sb2 = sbase + (uint32_t)st * STAGE_B;
        CPA(sb2 + sw0,          gah0 + k0);
        CPA(sb2 + sw1,          gah1 + k0);
        CPA(sb2 + OFF_AL + sw0, gal0 + k0);
        CPA(sb2 + OFF_AL + sw1, gal1 + k0);
        CPA(sb2 + OFF_BH + sw0, gbh0 + k0);
        CPA(sb2 + OFF_BH + sw1, gbh1 + k0);
        CPA(sb2 + OFF_BL + sw0, gbl0 + k0);
        CPA(sb2 + OFF_BL + sw1, gbl1 + k0);
    };

    float acc[4][4][4];
    #pragma unroll
    for (int i = 0; i < 4; i++)
        #pragma unroll
        for (int j = 0; j < 4; j++)
            #pragma unroll
            for (int e = 0; e < 4; e++) acc[i][j][e] = 0.0f;

    uint32_t arow[4], brow[2];
    #pragma unroll
    for (int i = 0; i < 4; i++) arow[i] = (uint32_t)(wm + i * 16 + (lid & 15));
    #pragma unroll
    for (int jp = 0; jp < 2; jp++)
        brow[jp] = (uint32_t)(wn + jp * 16 + (lid & 7) + ((lid >> 4) << 3));
    const uint32_t aco = (uint32_t)(lid >> 4);
    const uint32_t bco = (uint32_t)((lid >> 3) & 1);

    auto compute = [&](int buf) {
        const uint32_t bb = sbase + (uint32_t)buf * STAGE_B;
        #pragma unroll
        for (int ks2 = 0; ks2 < 2; ks2++) {
            uint32_t ah[4][4], al[4][4], bh[4][2], bl[4][2];
            #pragma unroll
            for (int i = 0; i < 4; i++) {
                uint32_t off = swz(arow[i], ks2 * 2 + aco);
                LDM4(ah[i], bb + off);
                LDM4(al[i], bb + OFF_AL + off);
            }
            #pragma unroll
            for (int jp = 0; jp < 2; jp++) {
                uint32_t off = swz(brow[jp], ks2 * 2 + bco);
                uint32_t r[4];
                LDM4(r, bb + OFF_BH + off);
                bh[2 * jp][0] = r[0]; bh[2 * jp][1] = r[1];
                bh[2 * jp + 1][0] = r[2]; bh[2 * jp + 1][1] = r[3];
                LDM4(r, bb + OFF_BL + off);
                bl[2 * jp][0] = r[0]; bl[2 * jp][1] = r[1];
                bl[2 * jp + 1][0] = r[2]; bl[2 * jp + 1][1] = r[3];
            }
            #pragma unroll
            for (int i = 0; i < 4; i++)
                #pragma unroll
                for (int j = 0; j < 4; j++) mma16(acc[i][j], ah[i], bl[j]);
            #pragma unroll
            for (int i = 0; i < 4; i++)
                #pragma unroll
                for (int j = 0; j < 4; j++) mma16(acc[i][j], al[i], bh[j]);
            #pragma unroll
            for (int i = 0; i < 4; i++)
                #pragma unroll
                for (int j = 0; j < 4; j++) mma16(acc[i][j], ah[i], bh[j]);
        }
    };

    const int NS = ksteps;

    issue(ks0 * BK, 0); CPC();
    issue((ks0 + 1) * BK, 1); CPC();

    #pragma unroll 1
    for (int s = 0; s < NS; s++) {
        if (s < NS - 1) { CPW(1); } else { CPW(0); }
        __syncthreads();
        compute(s % 3);
        if (s + 2 < NS) { issue((ks0 + s + 2) * BK, (s + 2) % 3); CPC(); }
    }

    // epilogue
    if (MODE == 1) {
        #pragma unroll
        for (int i = 0; i < 4; i++) {
            int row = bm + wm + i * 16 + g;
            #pragma unroll
            for (int j = 0; j < 4; j++) {
                int col = bn + wn + j * 8 + 2 * t;
                float* p0 = Cf + (size_t)row * 1024 + col;
                float* p1 = Cf + (size_t)(row + 8) * 1024 + col;
                REDADD(p0,     acc[i][j][0]);
                REDADD(p0 + 1, acc[i][j][1]);
                REDADD(p1,     acc[i][j][2]);
                REDADD(p1 + 1, acc[i][j][3]);
            }
        }
    } else if (MODE == 2) {
        // row = channel (0..1023), col = global token; write split planes [b][c][tok]
        #pragma unroll
        for (int i = 0; i < 4; i++) {
            int row = bm + wm + i * 16 + g;
            #pragma unroll
            for (int j = 0; j < 4; j++) {
                int col = bn + wn + j * 8 + 2 * t;
                int b2 = col >> 13;
                int tok = col & (Nt - 1);
                size_t ob = (size_t)b2 * ((size_t)Dd * Nt);
                #pragma unroll
                for (int e = 0; e < 2; e++) {
                    float v0 = acc[i][j][2 * e], v1 = acc[i][j][2 * e + 1];
                    bf16 h0 = __float2bfloat16_rn(v0);
                    bf16 h1 = __float2bfloat16_rn(v1);
                    bf16 l0 = __float2bfloat16_rn(v0 - __bfloat162float(h0));
                    bf16 l1 = __float2bfloat16_rn(v1 - __bfloat162float(h1));
                    size_t o = ob + (size_t)(row + 8 * e) * Nt + tok;
                    __nv_bfloat162 hv; hv.x = h0; hv.y = h1;
                    __nv_bfloat162 lv; lv.x = l0; lv.y = l1;
                    *(__nv_bfloat162*)(Ch + o) = hv;
                    *(__nv_bfloat162*)(Cl + o) = lv;
                }
            }
        }
    } else {
        #pragma unroll
        for (int i = 0; i < 4; i++) {
            int row = bm + wm + i * 16 + g;
            #pragma unroll
            for (int j = 0; j < 4; j++) {
                int col = bn + wn + j * 8 + 2 * t;
                *(float2*)(Cf + (size_t)row * 1024 + col) =
                    make_float2(acc[i][j][0], acc[i][j][1]);
                *(float2*)(Cf + (size_t)(row + 8) * 1024 + col) =
                    make_float2(acc[i][j][2], acc[i][j][3]);
            }
        }
    }
}

// ---------------- tensor-core Gram: G_bh partial over 512-token slice -----------
// Reads QKT split planes [b][c][tok]; A=B = 64 channels of head h.
// Block: 128 threads, 4 warps (2x2 of 32x32 warp tiles). k-chunk 64 tokens.
#define GPL 8192                       // plane bytes: 64 rows * 128 B
#define GSTG (2 * GPL)                 // stage: hi+lo
__global__ __launch_bounds__(128)
void gram_mma(const bf16* __restrict__ QKTh, const bf16* __restrict__ QKTl,
              float* __restrict__ Gpart)
{
    __shared__ __align__(16) char sm[3 * GSTG];   // 48 KB
    const int bh = blockIdx.x, sp = blockIdx.y;
    const int b = bh >> 4, h = bh & 15;
    const size_t base = (size_t)b * ((size_t)Dd * Nt) + (size_t)(h * DH) * Nt
                      + (size_t)sp * (Nt / NSPLIT);
    const bf16* Ah = QKTh + base;
    const bf16* Al = QKTl + base;

    const int tid = threadIdx.x;
    const int wid = tid >> 5, lid = tid & 31;
    const int g = lid >> 2, t = lid & 3;
    const int wm = (wid >> 1) * 32, wn = (wid & 1) * 32;
    const uint32_t sb = smem_u32(sm);

    // cp.async: row r (0..63 = channel), chunk cols c0..c0+3 (16B units)
    const uint32_t r = (uint32_t)tid >> 1;
    const uint32_t c0 = ((uint32_t)tid & 1) * 4;
    auto issue = [&](int kc, int st) {
        uint32_t s0 = sb + (uint32_t)st * GSTG;
        const bf16* ga = Ah + (size_t)r * Nt + kc * 64;
        const bf16* gl = Al + (size_t)r * Nt + kc * 64;
        #pragma unroll
        for (int c = 0; c < 4; c++) {
            uint32_t d = swz128(r, c0 + c);
            CPA(s0 + d,       ga + (c0 + c) * 8);
            CPA(s0 + GPL + d, gl + (c0 + c) * 8);
        }
    };

    float acc[2][4][4];
    #pragma unroll
    for (int i = 0; i < 2; i++)
        #pragma unroll
        for (int j = 0; j < 4; j++)
            #pragma unroll
            for (int e = 0; e < 4; e++) acc[i][j][e] = 0.0f;

    uint32_t arow[2], brow[2];
    #pragma unroll
    for (int i = 0; i < 2; i++) arow[i] = (uint32_t)(wm + i * 16 + (lid & 15));
    #pragma unroll
    for (int jp = 0; jp < 2; jp++)
        brow[jp] = (uint32_t)(wn + jp * 16 + (lid & 7) + ((lid >> 4) << 3));
    const uint32_t aco = (uint32_t)(lid >> 4);
    const uint32_t bco = (uint32_t)((lid >> 3) & 1);

    const int NC = (Nt / NSPLIT) / 64;   // 8 chunks

    issue(0, 0); CPC();
    issue(1, 1); CPC();

    #pragma unroll 1
    for (int kc = 0; kc < NC; kc++) {
        if (kc < NC - 1) { CPW(1); } else { CPW(0); }
        __syncthreads();
        uint32_t s0 = sb + (uint32_t)(kc % 3) * GSTG;
        #pragma unroll
        for (int ks = 0; ks < 4; ks++) {
            uint32_t ah[2][4], al2[2][4], bh2[4][2], bl2[4][2];
            #pragma unroll
            for (int i = 0; i < 2; i++) {
                uint32_t off = swz128(arow[i], ks * 2 + aco);
                LDM4(ah[i], s0 + off);
                LDM4(al2[i], s0 + GPL + off);
            }
            #pragma unroll
            for (int jp = 0; jp < 2; jp++) {
                uint32_t off = swz128(brow[jp], ks * 2 + bco);
                uint32_t rr[4];
                LDM4(rr, s0 + off);
                bh2[2 * jp][0] = rr[0]; bh2[2 * jp][1] = rr[1];
                bh2[2 * jp + 1][0] = rr[2]; bh2[2 * jp + 1][1] = rr[3];
                LDM4(rr, s0 + GPL + off);
                bl2[2 * jp][0] = rr[0]; bl2[2 * jp][1] = rr[1];
                bl2[2 * jp + 1][0] = rr[2]; bl2[2 * jp + 1][1] = rr[3];
            }
            #pragma unroll
            for (int i = 0; i < 2; i++)
                #pragma unroll
                for (int j = 0; j < 4; j++) mma16(acc[i][j], ah[i], bl2[j]);
            #pragma unroll
            for (int i = 0; i < 2; i++)
                #pragma unroll
                for (int j = 0; j < 4; j++) mma16(acc[i][j], al2[i], bh2[j]);
            #pragma unroll
            for (int i = 0; i < 2; i++)
                #pragma unroll
                for (int j = 0; j < 4; j++) mma16(acc[i][j], ah[i], bh2[j]);
        }
        if (kc + 2 < NC) { issue(kc + 2, (kc + 2) % 3); CPC(); }
    }

    float* gp = Gpart + (size_t)(bh * NSPLIT + sp) * (DH * DH);
    #pragma unroll
    for (int i = 0; i < 2; i++) {
        #pragma unroll
        for (int j = 0; j < 4; j++) {
            int c = wm + i * 16 + g;
            int d = wn + j * 8 + 2 * t;
            gp[c * DH + d]           = acc[i][j][0];
            gp[c * DH + d + 1]       = acc[i][j][1];
            gp[(c + 8) * DH + d]     = acc[i][j][2];
            gp[(c + 8) * DH + d + 1] = acc[i][j][3];
        }
    }
}

// ---------------- split fp32 -> bf16 hi/lo planes ------------------------------
__global__ __launch_bounds__(256)
void split_f32(const float* __restrict__ src, bf16* __restrict__ h, bf16* __restrict__ l)
{
    size_t i = ((size_t)blockIdx.x * 256 + threadIdx.x) * 4;
    float4 v = *(const float4*)(src + i);
    bf16 h0 = __float2bfloat16_rn(v.x), h1 = __float2bfloat16_rn(v.y);
    bf16 h2 = __float2bfloat16_rn(v.z), h3 = __float2bfloat16_rn(v.w);
    bf16 l0 = __float2bfloat16_rn(v.x - __bfloat162float(h0));
    bf16 l1 = __float2bfloat16_rn(v.y - __bfloat162float(h1));
    bf16 l2 = __float2bfloat16_rn(v.z - __bfloat162float(h2));
    bf16 l3 = __float2bfloat16_rn(v.w - __bfloat162float(h3));
    __nv_bfloat162 a, b;
    a.x = h0; a.y = h1; b.x = h2; b.y = h3;
    *(__nv_bfloat162*)(h + i) = a; *(__nv_bfloat162*)(h + i + 2) = b;
    a.x = l0; a.y = l1; b.x = l2; b.y = l3;
    *(__nv_bfloat162*)(l + i) = a; *(__nv_bfloat162*)(l + i + 2) = b;
}

// ---------------- Wqk transpose + split ----------------------------------------
__global__ __launch_bounds__(256)
void transpose_w(const float* __restrict__ W, bf16* __restrict__ WTh, bf16* __restrict__ WTl)
{
    __shared__ float tbuf[32][33];
    int bx = blockIdx.x * 32, by = blockIdx.y * 32;
    int tx = threadIdx.x & 31, ty = threadIdx.x >> 5;
    #pragma unroll
    for (int i = 0; i < 4; i++) {
        int r = ty + i * 8;
        tbuf[r][tx] = W[(size_t)(by + r) * Dd + bx + tx];
    }
    __syncthreads();
    #pragma unroll
    for (int i = 0; i < 4; i++) {
        int r = ty + i * 8;
        float v = tbuf[tx][r];
        bf16 h = __float2bfloat16_rn(v);
        bf16 l = __float2bfloat16_rn(v - __bfloat162float(h));
        size_t o = (size_t)(bx + r) * Dd + by + tx;
        WTh[o] = h; WTl[o] = l;
    }
}

// ---------------- reduce + softmax ----------------------------------------------
__global__ __launch_bounds__(256)
void softmax_kernel(const float* __restrict__ Gpart,
                    const float* __restrict__ tau,
                    float* __restrict__ attn)
{
    const int bh = blockIdx.x;
    const int h = bh & 15;
    __shared__ float G[DH * DH];
    const int tid = threadIdx.x;

    const float* base = Gpart + (size_t)bh * NSPLIT * (DH * DH);
    for (int e = tid; e < DH * DH; e += 256) {
        float s = 0.0f;
        #pragma unroll
        for (int p = 0; p < NSPLIT; p++) s += base[(size_t)p * (DH * DH) + e];
        G[e] = s;
    }
    __syncthreads();

    if (tid < DH) {
        const int c = tid;
        const float tauh = tau[h];
        const float scale = 0.011048543456039806f;
        const float qc = G[c * DH + c];
        float l[DH];
        float mx = -1e30f;
        #pragma unroll 8
        for (int d = 0; d < DH; d++) {
            float v = (2.0f * G[c * DH + d] - qc - G[d * DH + d]) * scale * tauh;
            l[d] = v;
            mx = fmaxf(mx, v);
        }
        float sum = 0.0f;
        #pragma unroll 8
        for (int d = 0; d < DH; d++) { float e = __expf(l[d] - mx); l[d] = e; sum += e; }
        const float inv = 1.0f / sum;
        float* ap = attn + (size_t)bh * (DH * DH) + c * DH;
        #pragma unroll 8
        for (int d = 0; d < DH; d++) ap[d] = l[d] * inv;
    }
}

// ---------------- fold attn into W_out, emit split M^T ---------------------------
__global__ __launch_bounds__(256)
void build_mT(const float* __restrict__ attn,
              const float* __restrict__ Wout,
              bf16* __restrict__ MTh, bf16* __restrict__ MTl)
{
    const int bh = blockIdx.y;
    const int b = bh >> 4, h = bh & 15;
    const int j0 = blockIdx.x * 128;

    __shared__ float Asm[DH * DH];
    __shared__ float Ws[DH][128];

    const int tid = threadIdx.x;
    const float* ap = attn + (size_t)bh * (DH * DH);
    for (int e = tid; e < DH * DH; e += 256) Asm[e] = ap[e];

    #pragma unroll
    for (int i = 0; i < 8; i++) {
        int idx = tid + i * 256;
        int r = idx >> 5;
        int c4 = (idx & 31) * 4;
        *(float4*)&Ws[r][c4] =
            *(const float4*)(Wout + (size_t)(h * DH + r) * Dd + j0 + c4);
    }
    __syncthreads();

    const int tx = tid & 15, ty = tid >> 4;
    float acc[8][4];
    #pragma unroll
    for (int i = 0; i < 8; i++)
        #pragma unroll
        for (int j = 0; j < 4; j++) acc[i][j] = 0.0f;

    for (int c = 0; c < DH; c++) {
        float4 av = *(float4*)&Asm[c * DH + tx * 4];
        #pragma unroll
        for (int i = 0; i < 8; i++) {
            float w = Ws[c][ty * 8 + i];
            acc[i][0] += w * av.x;
            acc[i][1] += w * av.y;
            acc[i][2] += w * av.z;
            acc[i][3] += w * av.w;
        }
    }

    bf16* Mh = MTh + (size_t)b * Dd * Dd;
    bf16* Ml = MTl + (size_t)b * Dd * Dd;
    #pragma unroll
    for (int i = 0; i < 8; i++) {
        int j = j0 + ty * 8 + i;
        size_t o = (size_t)j * Dd + h * DH + tx * 4;
        #pragma unroll
        for (int e = 0; e < 4; e++) {
            float v = acc[i][e];
            bf16 hh = __float2bfloat16_rn(v);
            bf16 ll = __float2bfloat16_rn(v - __bfloat162float(hh));
            Mh[o + e] = hh; Ml[o + e] = ll;
        }
    }
}

// ----------------------------------------------------------------------------------
extern "C" void kernel_launch(void* const* d_in, const int* in_sizes, int n_in,
                              void* d_out, int out_size)
{
    const float* x    = (const float*)d_in[0];
    const float* Wqk  = (const float*)d_in[1];
    const float* Wv   = (const float*)d_in[2];
    const float* Wout = (const float*)d_in[3];
    const float* tau  = (const float*)d_in[4];
    float* out = (float*)d_out;

    void *pxh, *pxl, *pqth, *pqtl, *pwth, *pwtl, *pwvh, *pwvl, *pmth, *pmtl,
         *pntf, *pnth, *pntl, *pg, *pa;
    cudaGetSymbolAddress(&pxh, g_xh);
    cudaGetSymbolAddress(&pxl, g_xl);
    cudaGetSymbolAddress(&pqth, g_qkth);
    cudaGetSymbolAddress(&pqtl, g_qktl);
    cudaGetSymbolAddress(&pwth, g_wth);
    cudaGetSymbolAddress(&pwtl, g_wtl);
    cudaGetSymbolAddress(&pwvh, g_wvh);
    cudaGetSymbolAddress(&pwvl, g_wvl);
    cudaGetSymbolAddress(&pmth, g_mth);
    cudaGetSymbolAddress(&pmtl, g_mtl);
    cudaGetSymbolAddress(&pntf, g_ntf);
    cudaGetSymbolAddress(&pnth, g_nth);
    cudaGetSymbolAddress(&pntl, g_ntl);
    cudaGetSymbolAddress(&pg, g_gpart);
    cudaGetSymbolAddress(&pa, g_attn);

    bf16 *Xh = (bf16*)pxh, *Xl = (bf16*)pxl;
    bf16 *QTh = (bf16*)pqth, *QTl = (bf16*)pqtl;
    bf16 *WTh = (bf16*)pwth, *WTl = (bf16*)pwtl;
    bf16 *WVh = (bf16*)pwvh, *WVl = (bf16*)pwvl;
    bf16 *MTh = (bf16*)pmth, *MTl = (bf16*)pmtl;
    float* NTf = (float*)pntf;
    bf16 *NTh = (bf16*)pnth, *NTl = (bf16*)pntl;
    float* Gp = (float*)pg;
    float* At = (float*)pa;

    cudaFuncSetAttribute(mma_gemm<0>, cudaFuncAttributeMaxDynamicSharedMemorySize, SMB);
    cudaFuncSetAttribute(mma_gemm<1>, cudaFuncAttributeMaxDynamicSharedMemorySize, SMB);
    cudaFuncSetAttribute(mma_gemm<2>, cudaFuncAttributeMaxDynamicSharedMemorySize, SMB);

    // 0a: split X
    split_f32<<<(size_t)Mrows * Dd / 1024, 256>>>(x, Xh, Xl);
    // 0b: split Wv (row-major == n-major B for NT GEMM)
    split_f32<<<(size_t)Dd * Dd / 1024, 256>>>(Wv, WVh, WVl);
    // 0c: transpose + split Wqk
    transpose_w<<<dim3(32, 32), 256>>>(Wqk, WTh, WTl);
    // 1: QKT[c, tok] = sum_k WT[c,k] * X[tok,k]  (A=WT, B=X, split-bf16 QKT store)
    mma_gemm<2><<<dim3(128, 8, 1), 256, SMB>>>(WTh, WTl, 0, Xh, Xl, 0,
                                               nullptr, nullptr, QTh, QTl, 128, 32);
    // 2: tensor-core Gram partials
    gram_mma<<<dim3(32, NSPLIT), 128>>>(QTh, QTl, Gp);
    // 3: reduce + softmax
    softmax_kernel<<<32, 256>>>(Gp, tau, At);
    // 4: fold attn into W_out (transposed, split)
    build_mT<<<dim3(8, 32), 256>>>(At, Wout, MTh, MTl);
    // 5: NT_b = MT_b @ Wv^T   (split-K=4, atomic fp32)
    cudaMemsetAsync(NTf, 0, (size_t)Bq * Dd * Dd * sizeof(float));
    mma_gemm<1><<<dim3(32, 8, 2), 256, SMB>>>(MTh, MTl, (size_t)Dd * Dd,
                                              WVh, WVl, 0,
                                              NTf, NTf + (size_t)Dd * Dd,
                                              nullptr, nullptr, 8, 8);
    // 5b: split NT to bf16 planes
    split_f32<<<(size_t)Bq * Dd * Dd / 1024, 256>>>(NTf, NTh, NTl);
    // 6: out_b = X_b @ N_b
    mma_gemm<0><<<dim3(8, 64, 2), 256, SMB>>>(Xh, Xl, (size_t)Nt * Dd,
                                              NTh, NTl, (size_t)Dd * Dd,
                                              out, out + (size_t)Nt * Dd,
                                              nullptr, nullptr, 8, 32);
}